// round 2
// baseline (speedup 1.0000x reference)
#include <cuda_runtime.h>
#include <cuda_bf16.h>

#define MAX_NODES 100000
#define IN_F 24
#define HID 64
#define F4_PER_ROW 6   // 24 floats = 6 float4

// Scratch (allocation-free rule: __device__ globals)
__device__ float  g_deg [MAX_NODES];
__device__ float  g_dinv[MAX_NODES];
__device__ float4 g_agg1[MAX_NODES * F4_PER_ROW];   // 9.6 MB, mostly L2-resident
__device__ float  g_y   [MAX_NODES];

// ---------------------------------------------------------------------------
__global__ void zero_deg_kernel(int n) {
    int i = blockIdx.x * blockDim.x + threadIdx.x;
    if (i < n) g_deg[i] = 0.0f;
}

// deg[d] += 1 for each edge (self-loop +1 folded into rsqrt later)
__global__ void deg_kernel(const int* __restrict__ dst, int E) {
    int e = blockIdx.x * blockDim.x + threadIdx.x;
    if (e < E) atomicAdd(&g_deg[dst[e]], 1.0f);
}

// dinv = rsqrt(indeg + 1); also initialize agg1 with the self-loop term
// agg1[i] = dinv[i]^2 * x[i]   (this doubles as the zero-init of agg1)
__global__ void dinv_selfloop_kernel(const float4* __restrict__ x4, int n) {
    int i = blockIdx.x * blockDim.x + threadIdx.x;
    if (i >= n) return;
    float d = rsqrtf(g_deg[i] + 1.0f);
    g_dinv[i] = d;
    float s = d * d;
    const float4* xr = x4 + (size_t)i * F4_PER_ROW;
    float4* ar = g_agg1 + (size_t)i * F4_PER_ROW;
#pragma unroll
    for (int k = 0; k < F4_PER_ROW; k++) {
        float4 v = xr[k];
        v.x *= s; v.y *= s; v.z *= s; v.w *= s;
        ar[k] = v;
    }
}

// Layer-1 aggregation on RAW features (linearity: segsum(norm*x[src]) @ W1)
// 6 x red.global.add.v4.f32 per edge
__global__ void scatter_x_kernel(const int* __restrict__ src,
                                 const int* __restrict__ dst,
                                 const float4* __restrict__ x4, int E) {
    int e = blockIdx.x * blockDim.x + threadIdx.x;
    if (e >= E) return;
    int s = src[e];
    int d = dst[e];
    float nw = g_dinv[s] * g_dinv[d];
    const float4* xr = x4 + (size_t)s * F4_PER_ROW;
    float4* ar = g_agg1 + (size_t)d * F4_PER_ROW;
#pragma unroll
    for (int k = 0; k < F4_PER_ROW; k++) {
        float4 v = xr[k];
        asm volatile("red.global.add.v4.f32 [%0], {%1, %2, %3, %4};"
                     :: "l"(ar + k),
                        "f"(v.x * nw), "f"(v.y * nw), "f"(v.z * nw), "f"(v.w * nw)
                     : "memory");
    }
}

// Per-node: h = agg1 @ W1 + b1; relu; y = h @ W2.
// Writes y[i] and out[i] = b2 + dinv[i]^2 * y[i]  (self-loop of layer 2).
__global__ void node_kernel(const float* __restrict__ W1,
                            const float* __restrict__ b1,
                            const float* __restrict__ W2,
                            const float* __restrict__ b2,
                            float* __restrict__ out, int n) {
    __shared__ float sW1[IN_F * HID];
    __shared__ float sB1[HID];
    __shared__ float sW2[HID];
    for (int t = threadIdx.x; t < IN_F * HID; t += blockDim.x) sW1[t] = W1[t];
    if (threadIdx.x < HID) {
        sB1[threadIdx.x] = b1[threadIdx.x];
        sW2[threadIdx.x] = W2[threadIdx.x];
    }
    __syncthreads();

    int i = blockIdx.x * blockDim.x + threadIdx.x;
    if (i >= n) return;

    float a[IN_F];
    const float4* ar = g_agg1 + (size_t)i * F4_PER_ROW;
#pragma unroll
    for (int k = 0; k < F4_PER_ROW; k++) {
        float4 v = ar[k];
        a[4 * k + 0] = v.x; a[4 * k + 1] = v.y; a[4 * k + 2] = v.z; a[4 * k + 3] = v.w;
    }

    float y = 0.0f;
#pragma unroll 8
    for (int j = 0; j < HID; j++) {
        float h = sB1[j];
#pragma unroll
        for (int k = 0; k < IN_F; k++) h = fmaf(a[k], sW1[k * HID + j], h);
        y = fmaf(fmaxf(h, 0.0f), sW2[j], y);
    }
    g_y[i] = y;
    float d = g_dinv[i];
    out[i] = b2[0] + d * d * y;   // self-loop term + bias; edges added next kernel
}

// Layer-2 aggregation: scalar per edge
__global__ void scatter_y_kernel(const int* __restrict__ src,
                                 const int* __restrict__ dst,
                                 float* __restrict__ out, int E) {
    int e = blockIdx.x * blockDim.x + threadIdx.x;
    if (e >= E) return;
    int s = src[e];
    int d = dst[e];
    atomicAdd(&out[d], g_dinv[s] * g_dinv[d] * g_y[s]);
}

// ---------------------------------------------------------------------------
extern "C" void kernel_launch(void* const* d_in, const int* in_sizes, int n_in,
                              void* d_out, int out_size) {
    const float* x  = (const float*)d_in[0];
    const int*   ei = (const int*)d_in[1];   // edge_index: JAX x64-disabled -> int32
    const float* W1 = (const float*)d_in[2];
    const float* b1 = (const float*)d_in[3];
    const float* W2 = (const float*)d_in[4];
    const float* b2 = (const float*)d_in[5];
    float* out = (float*)d_out;

    const int n = in_sizes[0] / IN_F;          // 100000
    const int E = in_sizes[1] / 2;             // 3200000
    const int* src = ei;
    const int* dst = ei + E;
    const float4* x4 = (const float4*)x;

    const int TB = 256;
    const int nb_n = (n + TB - 1) / TB;
    const int nb_e = (E + TB - 1) / TB;

    zero_deg_kernel     <<<nb_n, TB>>>(n);
    deg_kernel          <<<nb_e, TB>>>(dst, E);
    dinv_selfloop_kernel<<<nb_n, TB>>>(x4, n);
    scatter_x_kernel    <<<nb_e, TB>>>(src, dst, x4, E);
    node_kernel         <<<nb_n, TB>>>(W1, b1, W2, b2, out, n);
    scatter_y_kernel    <<<nb_e, TB>>>(src, dst, out, E);
}

// round 4
// speedup vs baseline: 1.4844x; 1.4844x over previous
#include <cuda_runtime.h>
#include <cuda_bf16.h>

#define NMAX 100000
#define EMAX 3200000
#define IN_F 24
#define HID  64

// Scratch (__device__ globals; allocation-free rule)
__device__ int   g_cnt [NMAX];        // in-degree (without self-loop)
__device__ int   g_off [NMAX];        // CSR offsets (mutated by fill; restored as off = g_off - cnt)
__device__ int   g_bsum[512];
__device__ int   g_bbase[512];
__device__ float g_dinv[NMAX];
__device__ float g_xs  [NMAX * IN_F]; // dinv[i] * x[i]
__device__ float g_agg [NMAX * IN_F]; // layer-1 aggregated features
__device__ float g_z   [NMAX];        // dinv[i] * y[i]
__device__ int   g_csr [EMAX];        // src indices grouped by dst

// ---------------------------------------------------------------------------
__global__ void zero_kernel(int n) {
    int i = blockIdx.x * blockDim.x + threadIdx.x;
    if (i < n) g_cnt[i] = 0;
}

__global__ void hist_kernel(const int* __restrict__ dst, int E) {
    int e = blockIdx.x * blockDim.x + threadIdx.x;
    if (e < E) atomicAdd(&g_cnt[dst[e]], 1);
}

// Block-local exclusive scan of counts; also dinv = rsqrt(cnt+1)
__global__ void scanA_kernel(int n) {
    __shared__ int sh[256];
    int t = threadIdx.x;
    int i = blockIdx.x * 256 + t;
    int v = (i < n) ? g_cnt[i] : 0;
    if (i < n) g_dinv[i] = rsqrtf((float)v + 1.0f);
    sh[t] = v; __syncthreads();
#pragma unroll
    for (int o = 1; o < 256; o <<= 1) {
        int a = (t >= o) ? sh[t - o] : 0;
        __syncthreads();
        sh[t] += a;
        __syncthreads();
    }
    if (i < n) g_off[i] = sh[t] - v;          // exclusive within block
    if (t == 255) g_bsum[blockIdx.x] = sh[255];
}

// Single-block exclusive scan of block sums (nb <= 512)
__global__ void scanB_kernel(int nb) {
    __shared__ int sh[512];
    int t = threadIdx.x;
    int v = (t < nb) ? g_bsum[t] : 0;
    sh[t] = v; __syncthreads();
#pragma unroll
    for (int o = 1; o < 512; o <<= 1) {
        int a = (t >= o) ? sh[t - o] : 0;
        __syncthreads();
        sh[t] += a;
        __syncthreads();
    }
    g_bbase[t] = sh[t] - v;
}

__global__ void scanC_kernel(int n) {
    int i = blockIdx.x * 256 + threadIdx.x;
    if (i < n) g_off[i] += g_bbase[blockIdx.x];
}

// xs = dinv[i] * x  (element-wise, coalesced)
__global__ void xs_kernel(const float* __restrict__ x, int total) {
    int idx = blockIdx.x * blockDim.x + threadIdx.x;
    if (idx < total) g_xs[idx] = x[idx] * g_dinv[idx / IN_F];
}

// Fill CSR: bump g_off[d] itself as cursor (afterwards g_off[d] = start + cnt[d])
__global__ void fill_kernel(const int* __restrict__ src,
                            const int* __restrict__ dst, int E) {
    int e = blockIdx.x * blockDim.x + threadIdx.x;
    if (e >= E) return;
    int s = src[e], d = dst[e];
    int pos = atomicAdd(&g_off[d], 1);
    g_csr[pos] = s;
}

// Pull layer-1: one warp per node, lanes 0..23 = features
__global__ void pull1_kernel(int n) {
    int wid = (blockIdx.x * blockDim.x + threadIdx.x) >> 5;
    if (wid >= n) return;
    int lane = threadIdx.x & 31;
    int deg  = g_cnt[wid];
    int base = g_off[wid] - deg;      // restore original offset
    int f = (lane < IN_F) ? lane : 0;
    float acc = g_xs[wid * IN_F + f]; // self-loop term (pre-scaled by dinv[wid])
    int j = 0;
    for (; j + 4 <= deg; j += 4) {
        int s0 = g_csr[base + j];
        int s1 = g_csr[base + j + 1];
        int s2 = g_csr[base + j + 2];
        int s3 = g_csr[base + j + 3];
        float v0 = g_xs[s0 * IN_F + f];
        float v1 = g_xs[s1 * IN_F + f];
        float v2 = g_xs[s2 * IN_F + f];
        float v3 = g_xs[s3 * IN_F + f];
        acc += v0 + v1 + v2 + v3;
    }
    for (; j < deg; j++) {
        int s = g_csr[base + j];
        acc += g_xs[s * IN_F + f];
    }
    if (lane < IN_F) g_agg[wid * IN_F + lane] = g_dinv[wid] * acc;
}

// Per-node: h = agg @ W1 + b1; relu; y = h @ W2; z = dinv * y
__global__ void node_kernel(const float* __restrict__ W1,
                            const float* __restrict__ b1,
                            const float* __restrict__ W2, int n) {
    __shared__ float sW1[IN_F * HID];
    __shared__ float sB1[HID];
    __shared__ float sW2[HID];
    for (int t = threadIdx.x; t < IN_F * HID; t += blockDim.x) sW1[t] = W1[t];
    if (threadIdx.x < HID) {
        sB1[threadIdx.x] = b1[threadIdx.x];
        sW2[threadIdx.x] = W2[threadIdx.x];
    }
    __syncthreads();

    int i = blockIdx.x * blockDim.x + threadIdx.x;
    if (i >= n) return;

    float a[IN_F];
    const float4* ar = (const float4*)(g_agg + (size_t)i * IN_F);
#pragma unroll
    for (int k = 0; k < IN_F / 4; k++) {
        float4 v = ar[k];
        a[4 * k + 0] = v.x; a[4 * k + 1] = v.y; a[4 * k + 2] = v.z; a[4 * k + 3] = v.w;
    }

    float y = 0.0f;
#pragma unroll 8
    for (int j = 0; j < HID; j++) {
        float h = sB1[j];
#pragma unroll
        for (int k = 0; k < IN_F; k++) h = fmaf(a[k], sW1[k * HID + j], h);
        y = fmaf(fmaxf(h, 0.0f), sW2[j], y);
    }
    g_z[i] = g_dinv[i] * y;
}

// Pull layer-2: warp per node, lane-strided neighbors + shfl reduce
__global__ void pull2_kernel(const float* __restrict__ b2,
                             float* __restrict__ out, int n) {
    int wid = (blockIdx.x * blockDim.x + threadIdx.x) >> 5;
    if (wid >= n) return;
    int lane = threadIdx.x & 31;
    int deg  = g_cnt[wid];
    int base = g_off[wid] - deg;
    float acc = 0.0f;
    for (int j = lane; j < deg; j += 32) {
        int s = g_csr[base + j];
        acc += g_z[s];
    }
#pragma unroll
    for (int o = 16; o; o >>= 1) acc += __shfl_xor_sync(0xffffffffu, acc, o);
    if (lane == 0) out[wid] = b2[0] + g_dinv[wid] * (g_z[wid] + acc);
}

// ---------------------------------------------------------------------------
extern "C" void kernel_launch(void* const* d_in, const int* in_sizes, int n_in,
                              void* d_out, int out_size) {
    const float* x  = (const float*)d_in[0];
    const int*   ei = (const int*)d_in[1];   // int32 edge_index [2, E]
    const float* W1 = (const float*)d_in[2];
    const float* b1 = (const float*)d_in[3];
    const float* W2 = (const float*)d_in[4];
    const float* b2 = (const float*)d_in[5];
    float* out = (float*)d_out;

    const int n = in_sizes[0] / IN_F;          // 100000
    const int E = in_sizes[1] / 2;             // 3200000
    const int* src = ei;
    const int* dst = ei + E;

    const int TB = 256;
    const int nb_n = (n + TB - 1) / TB;        // 391
    const int nb_e = (E + TB - 1) / TB;
    const int nb_x = (n * IN_F + TB - 1) / TB;
    const int nb_w = (n * 32 + TB - 1) / TB;   // warp-per-node grids

    zero_kernel <<<nb_n, TB>>>(n);
    hist_kernel <<<nb_e, TB>>>(dst, E);
    scanA_kernel<<<nb_n, TB>>>(n);
    scanB_kernel<<<1, 512>>>(nb_n);
    scanC_kernel<<<nb_n, TB>>>(n);
    xs_kernel   <<<nb_x, TB>>>(x, n * IN_F);
    fill_kernel <<<nb_e, TB>>>(src, dst, E);
    pull1_kernel<<<nb_w, TB>>>(n);
    node_kernel <<<nb_n, TB>>>(W1, b1, W2, n);
    pull2_kernel<<<nb_w, TB>>>(b2, out, n);
}

// round 5
// speedup vs baseline: 1.5270x; 1.0287x over previous
#include <cuda_runtime.h>
#include <cuda_bf16.h>

#define NMAX 100000
#define EMAX 3200000
#define IN_F 24
#define HID  64

// Scratch (__device__ globals; allocation-free rule)
__device__ int   g_cnt [NMAX];        // in-degree (without self-loop)
__device__ int   g_off [NMAX];        // CSR offsets (fill mutates; restore as off-cnt)
__device__ int   g_total;             // global CSR cursor for single-pass scan
__device__ float g_dinv[NMAX];
__device__ float g_xsp [NMAX * 32];   // dinv[i]*x[i], rows PADDED to 128B
__device__ float g_agg [NMAX * IN_F]; // layer-1 aggregated features (unpadded)
__device__ float g_z   [NMAX];        // dinv[i] * y[i]
__device__ int   g_csr [EMAX];        // src indices grouped by dst

// ---------------------------------------------------------------------------
__global__ void zero_kernel(int n) {
    int i = blockIdx.x * blockDim.x + threadIdx.x;
    if (i < n) g_cnt[i] = 0;
    if (i == 0) g_total = 0;
}

__global__ void hist_kernel(const int* __restrict__ dst, int E) {
    int e = blockIdx.x * blockDim.x + threadIdx.x;
    if (e < E) atomicAdd(&g_cnt[dst[e]], 1);
}

// Single-pass: block-local exclusive scan + atomic base grab; also dinv.
// (CSR segments land in block-arrival order -- still a valid disjoint layout.)
__global__ void scan_kernel(int n) {
    __shared__ int sh[256];
    __shared__ int s_base;
    int t = threadIdx.x;
    int i = blockIdx.x * 256 + t;
    int v = (i < n) ? g_cnt[i] : 0;
    if (i < n) g_dinv[i] = rsqrtf((float)v + 1.0f);
    sh[t] = v; __syncthreads();
#pragma unroll
    for (int o = 1; o < 256; o <<= 1) {
        int a = (t >= o) ? sh[t - o] : 0;
        __syncthreads();
        sh[t] += a;
        __syncthreads();
    }
    if (t == 255) s_base = atomicAdd(&g_total, sh[255]);
    __syncthreads();
    if (i < n) g_off[i] = s_base + sh[t] - v;   // exclusive start offset
}

// xs padded: g_xsp[i*32 + f] = (f<24) ? x[i*24+f]*dinv[i] : 0
__global__ void xs_kernel(const float* __restrict__ x, int n) {
    int idx = blockIdx.x * blockDim.x + threadIdx.x;
    if (idx >= n * 32) return;
    int i = idx >> 5, f = idx & 31;
    g_xsp[idx] = (f < IN_F) ? x[i * IN_F + f] * g_dinv[i] : 0.0f;
}

// Fill CSR: bump g_off[d] itself as cursor (afterwards g_off[d] = start + cnt[d])
__global__ void fill_kernel(const int* __restrict__ src,
                            const int* __restrict__ dst, int E) {
    int e = blockIdx.x * blockDim.x + threadIdx.x;
    if (e >= E) return;
    int pos = atomicAdd(&g_off[dst[e]], 1);
    g_csr[pos] = src[e];
}

// Pull layer-1: warp per node; 4 neighbor groups x 8 lanes; lanes q<6 hold float4 q.
// One LDG.128 gathers 4 padded rows (4 lines, 1 wavefront/edge).
__global__ void pull1_kernel(int n) {
    int wid = (blockIdx.x * blockDim.x + threadIdx.x) >> 5;
    if (wid >= n) return;
    int lane = threadIdx.x & 31;
    int g = lane >> 3;        // neighbor group 0..3
    int q = lane & 7;         // float4 slot, active q<6
    int deg  = g_cnt[wid];
    int base = g_off[wid] - deg;
    float4 acc = make_float4(0.f, 0.f, 0.f, 0.f);
#pragma unroll 2
    for (int j = 0; j < deg; j += 4) {
        int jj = j + g;
        if (jj < deg && q < 6) {
            int s = g_csr[base + jj];   // 4 consecutive ints/warp: 1 sector
            float4 v = *(const float4*)(g_xsp + ((size_t)s << 5) + (q << 2));
            acc.x += v.x; acc.y += v.y; acc.z += v.z; acc.w += v.w;
        }
    }
    // reduce across the 4 groups (lanes differing in bits 3,4)
#pragma unroll
    for (int o = 8; o <= 16; o <<= 1) {
        acc.x += __shfl_xor_sync(0xffffffffu, acc.x, o);
        acc.y += __shfl_xor_sync(0xffffffffu, acc.y, o);
        acc.z += __shfl_xor_sync(0xffffffffu, acc.z, o);
        acc.w += __shfl_xor_sync(0xffffffffu, acc.w, o);
    }
    if (lane < 6) {   // g==0, q==lane
        float4 sv = *(const float4*)(g_xsp + ((size_t)wid << 5) + (lane << 2));
        float di = g_dinv[wid];
        acc.x = di * (acc.x + sv.x);
        acc.y = di * (acc.y + sv.y);
        acc.z = di * (acc.z + sv.z);
        acc.w = di * (acc.w + sv.w);
        *(float4*)(g_agg + (size_t)wid * IN_F + (lane << 2)) = acc;
    }
}

// Per-node: h = agg @ W1 + b1; relu; y = h @ W2; z = dinv * y
__global__ void node_kernel(const float* __restrict__ W1,
                            const float* __restrict__ b1,
                            const float* __restrict__ W2, int n) {
    __shared__ float sW1[IN_F * HID];
    __shared__ float sB1[HID];
    __shared__ float sW2[HID];
    for (int t = threadIdx.x; t < IN_F * HID; t += blockDim.x) sW1[t] = W1[t];
    if (threadIdx.x < HID) {
        sB1[threadIdx.x] = b1[threadIdx.x];
        sW2[threadIdx.x] = W2[threadIdx.x];
    }
    __syncthreads();

    int i = blockIdx.x * blockDim.x + threadIdx.x;
    if (i >= n) return;

    float a[IN_F];
    const float4* ar = (const float4*)(g_agg + (size_t)i * IN_F);
#pragma unroll
    for (int k = 0; k < IN_F / 4; k++) {
        float4 v = ar[k];
        a[4 * k + 0] = v.x; a[4 * k + 1] = v.y; a[4 * k + 2] = v.z; a[4 * k + 3] = v.w;
    }

    float y = 0.0f;
#pragma unroll 8
    for (int j = 0; j < HID; j++) {
        float h = sB1[j];
#pragma unroll
        for (int k = 0; k < IN_F; k++) h = fmaf(a[k], sW1[k * HID + j], h);
        y = fmaf(fmaxf(h, 0.0f), sW2[j], y);
    }
    g_z[i] = g_dinv[i] * y;
}

// Pull layer-2: warp per node, lane-strided neighbors + shfl reduce
__global__ void pull2_kernel(const float* __restrict__ b2,
                             float* __restrict__ out, int n) {
    int wid = (blockIdx.x * blockDim.x + threadIdx.x) >> 5;
    if (wid >= n) return;
    int lane = threadIdx.x & 31;
    int deg  = g_cnt[wid];
    int base = g_off[wid] - deg;
    float acc = 0.0f;
    for (int j = lane; j < deg; j += 32) {
        acc += g_z[g_csr[base + j]];
    }
#pragma unroll
    for (int o = 16; o; o >>= 1) acc += __shfl_xor_sync(0xffffffffu, acc, o);
    if (lane == 0) out[wid] = b2[0] + g_dinv[wid] * (g_z[wid] + acc);
}

// ---------------------------------------------------------------------------
extern "C" void kernel_launch(void* const* d_in, const int* in_sizes, int n_in,
                              void* d_out, int out_size) {
    const float* x  = (const float*)d_in[0];
    const int*   ei = (const int*)d_in[1];   // int32 edge_index [2, E]
    const float* W1 = (const float*)d_in[2];
    const float* b1 = (const float*)d_in[3];
    const float* W2 = (const float*)d_in[4];
    const float* b2 = (const float*)d_in[5];
    float* out = (float*)d_out;

    const int n = in_sizes[0] / IN_F;          // 100000
    const int E = in_sizes[1] / 2;             // 3200000
    const int* src = ei;
    const int* dst = ei + E;

    const int TB = 256;
    const int nb_n = (n + TB - 1) / TB;
    const int nb_e = (E + TB - 1) / TB;
    const int nb_p = (n * 32 + TB - 1) / TB;   // padded xs / warp-per-node grids

    zero_kernel <<<nb_n, TB>>>(n);
    hist_kernel <<<nb_e, TB>>>(dst, E);
    scan_kernel <<<nb_n, TB>>>(n);
    xs_kernel   <<<nb_p, TB>>>(x, n);
    fill_kernel <<<nb_e, TB>>>(src, dst, E);
    pull1_kernel<<<nb_p, TB>>>(n);
    node_kernel <<<nb_n, TB>>>(W1, b1, W2, n);
    pull2_kernel<<<nb_p, TB>>>(b2, out, n);
}